// round 6
// baseline (speedup 1.0000x reference)
#include <cuda_runtime.h>
#include <cstdint>

#define TT 8192
#define HH 16
#define DD 128
#define HD (HH * DD)        // 2048
#define C3 (3 * HD)         // 6144
#define NCB 8               // column blocks per head
#define CPB 16              // columns per block
#define GS 8                // steps per smem stage
#define NP (TT / 2)         // pairs per head

typedef unsigned long long u64;

// ---------------- scratch (static device memory; no allocs allowed) --------
__device__ float g_q  [HH * TT * DD];   // [H][T][D]
__device__ float g_k  [HH * TT * DD];   // [H][T][D]
__device__ float g_dec[HH * TT * DD];   // [H][T][D]
__device__ float g_v  [HH * TT * DD];   // [H][T][D]
__device__ float g_b  [HH * TT];        // [H][T]
__device__ float g_c  [HH * NP * 4];    // [H][NP][4]: c, cq00, cq10, cq11

// ---------------- packed f32x2 helpers (sm_103a) ---------------------------
__device__ __forceinline__ u64 fma2(u64 a, u64 b, u64 c) {
    u64 d; asm("fma.rn.f32x2 %0, %1, %2, %3;" : "=l"(d) : "l"(a), "l"(b), "l"(c)); return d;
}
__device__ __forceinline__ u64 mul2(u64 a, u64 b) {
    u64 d; asm("mul.rn.f32x2 %0, %1, %2;" : "=l"(d) : "l"(a), "l"(b)); return d;
}
__device__ __forceinline__ u64 add2(u64 a, u64 b) {
    u64 d; asm("add.rn.f32x2 %0, %1, %2;" : "=l"(d) : "l"(a), "l"(b)); return d;
}
__device__ __forceinline__ float hsum2(u64 a) {
    float x, y; asm("mov.b64 {%0, %1}, %2;" : "=f"(x), "=f"(y) : "l"(a)); return x + y;
}
__device__ __forceinline__ u64 pack2(float x) {
    u64 d; asm("mov.b64 %0, {%1, %1};" : "=l"(d) : "f"(x)); return d;
}
__device__ __forceinline__ void cpa16(void* dst, const void* src) {
    unsigned d = (unsigned)__cvta_generic_to_shared(dst);
    asm volatile("cp.async.ca.shared.global [%0], [%1], 16;" :: "r"(d), "l"(src));
}
__device__ __forceinline__ float softplusf(float x) {
    return (x > 20.f) ? x : log1pf(expf(x));
}

// ============================================================================
// Phase 1: conv1d + SiLU, l2norm(q,k), gates  -> transposed [H][T][D] scratch
// ============================================================================
__global__ void prep_kernel(const float* __restrict__ xin,   // [T, 3HD]
                            const float* __restrict__ fg,    // [T, HD]
                            const float* __restrict__ beta,  // [T, H]
                            const float* __restrict__ cw,    // [3HD, 4]
                            const float* __restrict__ dtb,   // [H, D]
                            const float* __restrict__ alog)  // [H]
{
    const int t   = blockIdx.x;
    const int tid = threadIdx.x;                 // 256 threads

    __shared__ float sbuf[C3];
    __shared__ float snorm[32];
    __shared__ float snegA[HH];

    if (tid < HH) snegA[tid] = -expf(alog[tid]);

    const float4* x4  = (const float4*)xin;      // [T, 1536]
    const float4* w4  = (const float4*)cw;
    float4* sbuf4 = (float4*)sbuf;

    #pragma unroll
    for (int it = 0; it < 6; it++) {
        int c4 = tid + it * 256;                 // 0..1535
        float4 w0 = w4[c4 * 4 + 0];
        float4 w1 = w4[c4 * 4 + 1];
        float4 w2 = w4[c4 * 4 + 2];
        float4 w3 = w4[c4 * 4 + 3];
        float4 a0 = x4[(size_t)t * 1536 + c4];
        float4 acc;
        acc.x = a0.x * w0.w; acc.y = a0.y * w1.w;
        acc.z = a0.z * w2.w; acc.w = a0.w * w3.w;
        if (t >= 1) {
            float4 a = x4[(size_t)(t - 1) * 1536 + c4];
            acc.x += a.x * w0.z; acc.y += a.y * w1.z;
            acc.z += a.z * w2.z; acc.w += a.w * w3.z;
        }
        if (t >= 2) {
            float4 a = x4[(size_t)(t - 2) * 1536 + c4];
            acc.x += a.x * w0.y; acc.y += a.y * w1.y;
            acc.z += a.z * w2.y; acc.w += a.w * w3.y;
        }
        if (t >= 3) {
            float4 a = x4[(size_t)(t - 3) * 1536 + c4];
            acc.x += a.x * w0.x; acc.y += a.y * w1.x;
            acc.z += a.z * w2.x; acc.w += a.w * w3.x;
        }
        acc.x = acc.x / (1.f + expf(-acc.x));
        acc.y = acc.y / (1.f + expf(-acc.y));
        acc.z = acc.z / (1.f + expf(-acc.z));
        acc.w = acc.w / (1.f + expf(-acc.w));
        sbuf4[c4] = acc;
    }
    __syncthreads();

    const int wid = tid >> 5, lane = tid & 31;
    for (int g = wid; g < 32; g += 8) {
        const int base = g * 128;
        float v0 = sbuf[base + lane];
        float v1 = sbuf[base + 32 + lane];
        float v2 = sbuf[base + 64 + lane];
        float v3 = sbuf[base + 96 + lane];
        float ss = v0 * v0 + v1 * v1 + v2 * v2 + v3 * v3;
        #pragma unroll
        for (int off = 16; off > 0; off >>= 1)
            ss += __shfl_xor_sync(0xffffffffu, ss, off);
        if (lane == 0) snorm[g] = rsqrtf(ss + 1e-6f);
    }
    __syncthreads();

    const float qscale = 0.08838834764831845f;   // D^-0.5
    #pragma unroll
    for (int it = 0; it < 6; it++) {
        int c4 = tid + it * 256;
        int c  = c4 * 4;
        float4 val = sbuf4[c4];
        if (c < HD) {
            int h = c >> 7, d = c & 127;
            float sc = snorm[h] * qscale;
            val.x *= sc; val.y *= sc; val.z *= sc; val.w *= sc;
            ((float4*)g_q)[((size_t)h * TT + t) * 32 + (d >> 2)] = val;
        } else if (c < 2 * HD) {
            int cc = c - HD; int h = cc >> 7, d = cc & 127;
            float sc = snorm[16 + h];
            val.x *= sc; val.y *= sc; val.z *= sc; val.w *= sc;
            ((float4*)g_k)[((size_t)h * TT + t) * 32 + (d >> 2)] = val;
        } else {
            int cc = c - 2 * HD; int h = cc >> 7, d = cc & 127;
            ((float4*)g_v)[((size_t)h * TT + t) * 32 + (d >> 2)] = val;
        }
    }

    const float4* fg4  = (const float4*)fg;
    const float4* dtb4 = (const float4*)dtb;
    #pragma unroll
    for (int it = 0; it < 2; it++) {
        int c4 = tid + it * 256;                 // 0..511
        int h  = (c4 * 4) >> 7;
        float na = snegA[h];
        float4 gg = fg4[(size_t)t * 512 + c4];
        float4 bb = dtb4[c4];
        float4 r;
        r.x = expf(na * softplusf(gg.x + bb.x));
        r.y = expf(na * softplusf(gg.y + bb.y));
        r.z = expf(na * softplusf(gg.z + bb.z));
        r.w = expf(na * softplusf(gg.w + bb.w));
        ((float4*)g_dec)[((size_t)h * TT + t) * 32 + (((c4 * 4) & 127) >> 2)] = r;
    }
    if (tid < HH)
        g_b[tid * TT + t] = 1.f / (1.f + expf(-beta[(size_t)t * HH + tid]));
}

// ============================================================================
// Phase 1b: input-only pair scalars. One warp per pair.
//   kp = d1∘k0;  c=k1·kp, cq00=q0·k0, cq10=q1·kp, cq11=q1·k1
// ============================================================================
__global__ void __launch_bounds__(128)
pair_scalars_kernel()
{
    const int h    = blockIdx.y;
    const int p    = blockIdx.x * 4 + (threadIdx.x >> 5);
    const int lane = threadIdx.x & 31;

    const size_t b0 = ((size_t)h * TT + 2 * p) * DD;
    const float4 K0 = ((const float4*)(g_k   + b0))[lane];
    const float4 K1 = ((const float4*)(g_k   + b0 + DD))[lane];
    const float4 Dd = ((const float4*)(g_dec + b0 + DD))[lane];
    const float4 Q0 = ((const float4*)(g_q   + b0))[lane];
    const float4 Q1 = ((const float4*)(g_q   + b0 + DD))[lane];

    float4 kp;
    kp.x = Dd.x * K0.x; kp.y = Dd.y * K0.y;
    kp.z = Dd.z * K0.z; kp.w = Dd.w * K0.w;

    float c    = K1.x * kp.x + K1.y * kp.y + K1.z * kp.z + K1.w * kp.w;
    float cq00 = Q0.x * K0.x + Q0.y * K0.y + Q0.z * K0.z + Q0.w * K0.w;
    float cq10 = Q1.x * kp.x + Q1.y * kp.y + Q1.z * kp.z + Q1.w * kp.w;
    float cq11 = Q1.x * K1.x + Q1.y * K1.y + Q1.z * K1.z + Q1.w * K1.w;

    #pragma unroll
    for (int off = 16; off > 0; off >>= 1) {
        c    += __shfl_xor_sync(0xffffffffu, c,    off);
        cq00 += __shfl_xor_sync(0xffffffffu, cq00, off);
        cq10 += __shfl_xor_sync(0xffffffffu, cq10, off);
        cq11 += __shfl_xor_sync(0xffffffffu, cq11, off);
    }

    if (lane == 0)
        ((float4*)g_c)[(size_t)h * NP + p] = make_float4(c, cq00, cq10, cq11);
}

// ============================================================================
// Phase 2: pair-step scan. 2 critical shfl reductions per pair; output
// reductions deferred past the state update; input-only scalars precomputed.
// ============================================================================

#define LOAD8(R, arr, buf, i) do {                                          \
    const ulonglong2* _p = &arr[buf][i][ss];                                \
    ulonglong2 _c0 = _p[0], _c1 = _p[8], _c2 = _p[16], _c3 = _p[24];        \
    R[0]=_c0.x; R[1]=_c0.y; R[2]=_c1.x; R[3]=_c1.y;                         \
    R[4]=_c2.x; R[5]=_c2.y; R[6]=_c3.x; R[7]=_c3.y;                         \
} while (0)

#define PREFETCH(buf, t0) do {                                              \
    _Pragma("unroll")                                                       \
    for (int _j = 0; _j < 2; _j++) {                                        \
        int _c = tid + _j * 128;                                            \
        int _st = _c >> 5, _cc = _c & 31;                                   \
        int _pos = ((_cc & 3) << 3) | (_cc >> 2);                           \
        size_t _go = (size_t)((t0) + _st) * DD + _cc * 4;                   \
        cpa16(&sk[buf][_st][_pos], kg + _go);                               \
        cpa16(&sd[buf][_st][_pos], dg + _go);                               \
        cpa16(&sq[buf][_st][_pos], qg + _go);                               \
    }                                                                       \
    if (tid < 32) {                                                         \
        int _st = tid >> 2, _part = tid & 3;                                \
        cpa16(&sv[buf][_st][_part * 4],                                     \
              vg + (size_t)((t0) + _st) * DD + _part * 4);                  \
    } else if (tid < 34) {                                                  \
        int _j = tid - 32;                                                  \
        cpa16(&sb[buf][_j * 4], bg + (t0) + _j * 4);                        \
    } else if (tid < 38) {                                                  \
        int _pp = tid - 34;                                                 \
        cpa16(&scf[buf][_pp], cg + ((size_t)((t0) >> 1) + _pp) * 4);        \
    }                                                                       \
} while (0)

__global__ void __launch_bounds__(128, 1)
kda_scan_kernel(float* __restrict__ out)
{
    __shared__ __align__(16) ulonglong2 sk[2][GS][32];
    __shared__ __align__(16) ulonglong2 sd[2][GS][32];
    __shared__ __align__(16) ulonglong2 sq[2][GS][32];
    __shared__ __align__(16) float      sv[2][GS][16];
    __shared__ __align__(16) float      sb[2][GS];
    __shared__ __align__(16) float4     scf[2][GS / 2];

    const int h   = blockIdx.y;
    const int cb  = blockIdx.x;
    const int tid = threadIdx.x;
    const int cl  = tid >> 3;            // 0..15 column within block
    const int s   = tid & 7;             // k-subrange 0..7
    const int ss  = s;
    const int col = cb * CPB + cl;

    const size_t hbase = (size_t)h * TT * DD;
    const float* kg = g_k   + hbase;
    const float* dg = g_dec + hbase;
    const float* qg = g_q   + hbase;
    const float* vg = g_v   + hbase + cb * CPB;
    const float* bg = g_b   + (size_t)h * TT;
    const float* cg = g_c   + (size_t)h * NP * 4;
    float* op = out + (size_t)h * DD + col;     // + t*H*D per step

    u64 st[8];
    #pragma unroll
    for (int i = 0; i < 8; i++) st[i] = 0ull;

    PREFETCH(0, 0);
    asm volatile("cp.async.commit_group;" ::: "memory");
    PREFETCH(1, GS);
    asm volatile("cp.async.commit_group;" ::: "memory");

    #pragma unroll 1
    for (int t0 = 0; t0 < TT; t0 += GS) {
        const int buf = (t0 >> 3) & 1;
        asm volatile("cp.async.wait_group 1;" ::: "memory");
        __syncthreads();

        #pragma unroll
        for (int i = 0; i < GS; i += 2) {
            const int tcur = t0 + i;
            float b0f = sb[buf][i],     v0 = sv[buf][i][cl];
            float b1f = sb[buf][i + 1], v1 = sv[buf][i + 1][cl];
            float4 csc = scf[buf][i >> 1];   // c, cq00, cq10, cq11

            // P = D0∘S
            u64 D0[8];  LOAD8(D0, sd, buf, i);
            u64 P[8];
            #pragma unroll
            for (int j = 0; j < 8; j++) P[j] = mul2(D0[j], st[j]);

            // km_t = k0ᵀP (critical), o0p = q0ᵀP (deferred)
            u64 K0[8];  LOAD8(K0, sk, buf, i);
            u64 Q0[8];  LOAD8(Q0, sq, buf, i);
            u64 a0 = 0, a1 = 0, x0 = 0, x1 = 0;
            #pragma unroll
            for (int j = 0; j < 8; j += 2) {
                a0 = fma2(K0[j], P[j], a0);  a1 = fma2(K0[j+1], P[j+1], a1);
                x0 = fma2(Q0[j], P[j], x0);  x1 = fma2(Q0[j+1], P[j+1], x1);
            }

            // kp = D1∘K0, P2 = D1∘P (in place)
            u64 D1[8];  LOAD8(D1, sd, buf, i + 1);
            u64 kp[8];
            #pragma unroll
            for (int j = 0; j < 8; j++) {
                kp[j] = mul2(D1[j], K0[j]);
                P[j]  = mul2(D1[j], P[j]);
            }

            // km_a = k1ᵀP2 (critical), o1p = q1ᵀP2 (deferred)
            u64 K1[8];  LOAD8(K1, sk, buf, i + 1);
            u64 Q1[8];  LOAD8(Q1, sq, buf, i + 1);
            u64 e0 = 0, e1 = 0, y0 = 0, y1 = 0;
            #pragma unroll
            for (int j = 0; j < 8; j += 2) {
                e0 = fma2(K1[j], P[j], e0);  e1 = fma2(K1[j+1], P[j+1], e1);
                y0 = fma2(Q1[j], P[j], y0);  y1 = fma2(Q1[j+1], P[j+1], y1);
            }

            // ---- critical reductions only (2 values, 3 rounds) ----
            float rkm0 = hsum2(add2(a0, a1));
            float rkm1 = hsum2(add2(e0, e1));
            #pragma unroll
            for (int off = 1; off < 8; off <<= 1) {
                rkm0 += __shfl_xor_sync(0xffffffffu, rkm0, off);
                rkm1 += __shfl_xor_sync(0xffffffffu, rkm1, off);
            }

            // scalar recurrence
            float d0 = b0f * (v0 - rkm0);
            float d1 = b1f * (v1 - rkm1 - csc.x * d0);
            u64 dd0 = pack2(d0), dd1 = pack2(d1);

            // state update (critical)
            #pragma unroll
            for (int j = 0; j < 8; j++)
                st[j] = fma2(K1[j], dd1, fma2(kp[j], dd0, P[j]));

            // ---- deferred output reductions (overlap next pair) ----
            float ro0 = hsum2(add2(x0, x1));
            float ro1 = hsum2(add2(y0, y1));
            #pragma unroll
            for (int off = 1; off < 8; off <<= 1) {
                ro0 += __shfl_xor_sync(0xffffffffu, ro0, off);
                ro1 += __shfl_xor_sync(0xffffffffu, ro1, off);
            }
            if (s == 0) {
                op[(size_t)tcur * HD]       = fmaf(csc.y, d0, ro0);
                op[(size_t)(tcur + 1) * HD] = fmaf(csc.w, d1, fmaf(csc.z, d0, ro1));
            }
        }

        __syncthreads();
        if (t0 + 2 * GS < TT) {
            PREFETCH(buf, t0 + 2 * GS);
        }
        asm volatile("cp.async.commit_group;" ::: "memory");
    }
}

// ============================================================================
extern "C" void kernel_launch(void* const* d_in, const int* in_sizes, int n_in,
                              void* d_out, int out_size)
{
    const float* mixed = (const float*)d_in[0];   // [T, 3HD]
    const float* fg    = (const float*)d_in[1];   // [T, HD]
    const float* beta  = (const float*)d_in[2];   // [T, H]
    const float* cw    = (const float*)d_in[3];   // [3HD, 4]
    const float* dtb   = (const float*)d_in[4];   // [H, D]
    const float* alog  = (const float*)d_in[5];   // [H]
    float* out = (float*)d_out;                   // [T, H, D] f32

    prep_kernel<<<TT, 256>>>(mixed, fg, beta, cw, dtb, alog);
    pair_scalars_kernel<<<dim3(NP / 4, HH), 128>>>();
    kda_scan_kernel<<<dim3(NCB, HH), 128>>>(out);
}